// round 16
// baseline (speedup 1.0000x reference)
#include <cuda_runtime.h>

#define H    4096
#define IN   512
#define OUT  64
#define NJ4  (H / 4)       // 1024 float4 columns
#define GY   222           // k-stripes
#define NSB  444           // stripe blocks (bids 0..443)
#define NRB  128           // reducer blocks (bids 444..571) — co-resident!

// Device-global scratch (no allocations allowed).
__device__ float4   g_part[(size_t)GY * NJ4];  // ~3.6 MB
__device__ float    g_x[H];
__device__ unsigned g_done;    // +NSB per launch (stripe blocks)
__device__ unsigned g_rtkt;    // +NRB per launch (reducer tickets)

// ---------------------------------------------------------------------------
// Kernel 1 (572 blocks — ALL co-resident at 4 CTAs/SM, 592 slots):
//  [0,444)   stripe:  GEMV partials, R8's measured pattern untouched
//                     (8-wide threads, v8 evict_last hebb, plain w/plas).
//  [444,572) reducer: i2h dots for own 32 columns FIRST (overlaps the
//                     stream — resident from wave 1), ticket-wait, reduce
//                     partials, x = relu(i2h + bias + sum). i2h rows ==
//                     own x columns, so dots live in smem (no g_init).
// ---------------------------------------------------------------------------
__global__ void __launch_bounds__(256, 4)
k_main(const float* __restrict__ hidden, const float* __restrict__ hebb,
       const float* __restrict__ w,      const float* __restrict__ plas,
       const float* __restrict__ inp,    const float* __restrict__ W_i2h,
       const float* __restrict__ b_i2h,  float* __restrict__ x_out) {
    int b = blockIdx.x, t = threadIdx.x;

    if (b < NSB) {
        // ================= stripe: GEMV partial (R8 pattern) =============
        int stripe = b >> 1;
        int j8 = (b & 1) * 256 + t;            // 0..511
        int k0 = (stripe * H) / GY;
        int k1 = ((stripe + 1) * H) / GY;      // ~18-19 rows

        const float4* w4 = (const float4*)w;
        const float4* p4 = (const float4*)plas;
        const float4* h4 = (const float4*)hebb;

        float4 acc0 = make_float4(0.f, 0.f, 0.f, 0.f);
        float4 acc1 = make_float4(0.f, 0.f, 0.f, 0.f);
        size_t fbase = (size_t)j8 * 2;
#pragma unroll 4
        for (int r = k0; r < k1; ++r) {
            size_t idx = (size_t)r * NJ4 + fbase;
            float hk = __ldg(hidden + r);
            float4 a0 = w4[idx], a1 = w4[idx + 1];
            float4 b0 = p4[idx], b1 = p4[idx + 1];
            float4 c0, c1;
            asm volatile(
                "ld.global.nc.L2::evict_last.v8.b32 "
                "{%0,%1,%2,%3,%4,%5,%6,%7}, [%8];"
                : "=f"(c0.x), "=f"(c0.y), "=f"(c0.z), "=f"(c0.w),
                  "=f"(c1.x), "=f"(c1.y), "=f"(c1.z), "=f"(c1.w)
                : "l"(h4 + idx));
            acc0.x += hk * fmaf(b0.x, c0.x, a0.x);
            acc0.y += hk * fmaf(b0.y, c0.y, a0.y);
            acc0.z += hk * fmaf(b0.z, c0.z, a0.z);
            acc0.w += hk * fmaf(b0.w, c0.w, a0.w);
            acc1.x += hk * fmaf(b1.x, c1.x, a1.x);
            acc1.y += hk * fmaf(b1.y, c1.y, a1.y);
            acc1.z += hk * fmaf(b1.z, c1.z, a1.z);
            acc1.w += hk * fmaf(b1.w, c1.w, a1.w);
        }
        size_t o = (size_t)stripe * NJ4 + fbase;
        g_part[o]     = acc0;
        g_part[o + 1] = acc1;
        __threadfence();
        __syncthreads();
        if (t == 0) atomicAdd(&g_done, 1u);
        return;
    }

    // ================= reducer: i2h (overlapped) + x finalize =============
    {
        __shared__ float4 sp[32][8];
        __shared__ float4 stot[8];
        __shared__ float  sdot[32];      // i2h + bias for own 32 columns
        int rb = b - NSB;                // 0..127
        int j4base = rb * 8;             // 8 f4 cols = 32 scalar cols
        int j0 = rb * 32;                // first scalar column / i2h row

        // ---- i2h dots first: runs DURING the stream (co-resident) ----
        int wrp = t >> 5, lane = t & 31;
        const float4* in4 = (const float4*)inp;
#pragma unroll
        for (int c = 0; c < 4; ++c) {
            int row = j0 + wrp * 4 + c;
            const float4* wr = (const float4*)(W_i2h + (size_t)row * IN);
            float d = 0.f;
#pragma unroll
            for (int q = 0; q < (IN / 4) / 32; ++q) {   // 4 iters
                float4 aa = wr[lane + q * 32];
                float4 bb = in4[lane + q * 32];
                d += aa.x * bb.x + aa.y * bb.y + aa.z * bb.z + aa.w * bb.w;
            }
#pragma unroll
            for (int o = 16; o; o >>= 1) d += __shfl_down_sync(0xffffffffu, d, o);
            if (lane == 0) sdot[wrp * 4 + c] = d + b_i2h[row];
        }

        // ---- wait for all stripe blocks of THIS launch ----
        if (t == 0) {
            unsigned tk = atomicAdd(&g_rtkt, 1u);
            unsigned target = (tk / NRB + 1u) * NSB;
            volatile unsigned* p = &g_done;
            while (*p < target) __nanosleep(64);
        }
        __syncthreads();
        __threadfence();

        // ---- reduce partials (coalesced 128B rows) ----
        int j4loc = t & 7;
        int grp   = t >> 3;              // 0..31
        float4 acc = make_float4(0.f, 0.f, 0.f, 0.f);
#pragma unroll
        for (int q = 0; q < (GY + 31) / 32; ++q) {       // 7 iters
            int kb = grp + 32 * q;
            if (kb < GY) {
                float4 v = g_part[(size_t)kb * NJ4 + j4base + j4loc];
                acc.x += v.x; acc.y += v.y; acc.z += v.z; acc.w += v.w;
            }
        }
        sp[grp][j4loc] = acc;
        __syncthreads();
        if (t < 8) {
            float4 t4 = make_float4(0.f, 0.f, 0.f, 0.f);
#pragma unroll
            for (int g = 0; g < 32; ++g) {
                float4 v = sp[g][t];
                t4.x += v.x; t4.y += v.y; t4.z += v.z; t4.w += v.w;
            }
            stot[t] = t4;
        }
        __syncthreads();
        if (t < 32) {
            int jl = t >> 2, comp = t & 3;
            float4 t4 = stot[jl];
            float part = (comp == 0) ? t4.x : (comp == 1) ? t4.y
                       : (comp == 2) ? t4.z : t4.w;
            int j = j0 + t;
            float v = fmaxf(part + sdot[t], 0.f);
            g_x[j]   = v;
            x_out[j] = v;
        }
    }
}

// ---------------------------------------------------------------------------
// Kernel 2: hebb update (R14's 20.35us path) + out-head on 64 extra tail
// blocks. __launch_bounds__(256, 8) caps regs at 32 so the out-head branch
// cannot sink the hebb path's occupancy (R13's 23.4us mistake); the out
// blocks spill a little — 64 of 16448 blocks, negligible.
// ---------------------------------------------------------------------------
__global__ void __launch_bounds__(256, 8)
k_hebb_out(const float* __restrict__ hidden,
           const float* __restrict__ hebb,
           const float* __restrict__ learn_p,
           const float* __restrict__ W_h2o,
           const float* __restrict__ b_h2o,
           float* __restrict__ hebb_out,
           float* __restrict__ out) {
    int b = blockIdx.x, t = threadIdx.x;

    if (b < (H * H / 4) / 256) {
        // ---- hebb update (pure streaming path, 26 regs) ----
        int idx = b * 256 + t;              // float4 index over H*H/4
        int k   = idx >> 10;
        int jc  = idx & 1023;
        float learn = __ldg(learn_p);
        float hk    = __ldg(hidden + k);
        float4 hb = ((const float4*)hebb)[idx];
        float4 xv = ((const float4*)g_x)[jc];
        float a = 1.f - learn;
        float s = learn * hk;
        float4 o4;
        o4.x = fmaf(a, hb.x, s * xv.x);
        o4.y = fmaf(a, hb.y, s * xv.y);
        o4.z = fmaf(a, hb.z, s * xv.z);
        o4.w = fmaf(a, hb.w, s * xv.w);
        ((float4*)hebb_out)[idx] = o4;
        return;
    }

    // ---- output head (extra tail blocks; same wave count => free) ----
    __shared__ float red[8];
    int o = b - (H * H / 4) / 256;          // 0..63
    const float4* wr = (const float4*)(W_h2o + (size_t)o * H);
    const float4* x4 = (const float4*)g_x;
    float acc = 0.f;
#pragma unroll
    for (int q = 0; q < NJ4 / 256; ++q) {
        float4 aa = wr[t + q * 256];
        float4 bb = x4[t + q * 256];
        acc += aa.x * bb.x + aa.y * bb.y + aa.z * bb.z + aa.w * bb.w;
    }
#pragma unroll
    for (int s = 16; s; s >>= 1) acc += __shfl_down_sync(0xffffffffu, acc, s);
    if ((t & 31) == 0) red[t >> 5] = acc;
    __syncthreads();
    if (t == 0) {
        float v = red[0] + red[1] + red[2] + red[3] +
                  red[4] + red[5] + red[6] + red[7];
        out[o] = tanhf(v + b_h2o[o]);
    }
}

// ---------------------------------------------------------------------------
// Inputs: 0 inp, 1 hidden, 2 hebb, 3 W_i2h, 4 b_i2h, 5 w, 6 plas,
//         7 learn, 8 W_h2o, 9 b_h2o
// Output: [out(64) | x(4096) | hebb_new(16777216)]
// ---------------------------------------------------------------------------
extern "C" void kernel_launch(void* const* d_in, const int* in_sizes, int n_in,
                              void* d_out, int out_size) {
    const float* inp    = (const float*)d_in[0];
    const float* hidden = (const float*)d_in[1];
    const float* hebb   = (const float*)d_in[2];
    const float* W_i2h  = (const float*)d_in[3];
    const float* b_i2h  = (const float*)d_in[4];
    const float* w      = (const float*)d_in[5];
    const float* plas   = (const float*)d_in[6];
    const float* learn  = (const float*)d_in[7];
    const float* W_h2o  = (const float*)d_in[8];
    const float* b_h2o  = (const float*)d_in[9];

    float* out      = (float*)d_out;
    float* x_out    = out + OUT;
    float* hebb_out = out + OUT + H;

    // Kernel 1: GEMV partials + overlapped i2h + x-finalize (co-resident)
    k_main<<<NSB + NRB, 256>>>(hidden, hebb, w, plas, inp,
                               W_i2h, b_i2h, x_out);

    // Kernel 2: hebb update + out-head (reg-capped)
    k_hebb_out<<<(H * H / 4) / 256 + OUT, 256>>>(hidden, hebb, learn,
                                                 W_h2o, b_h2o, hebb_out, out);
}

// round 17
// speedup vs baseline: 1.0428x; 1.0428x over previous
#include <cuda_runtime.h>

#define H    4096
#define IN   512
#define OUT  64
#define NJ4  (H / 4)       // 1024 float4 columns
#define GY   296           // k-stripes
#define NSB  592           // stripe blocks in k1
#define NRB  128           // reducer blocks in k2

// Device-global scratch (no allocations allowed).
__device__ float4   g_part[(size_t)GY * NJ4];  // ~4.85 MB
__device__ float    g_x[H];
__device__ float    g_oacc[OUT];
__device__ unsigned g_done2;   // +NRB per launch (reducers done)
__device__ unsigned g_otkt;    // +1   per launch (finalize ticket)

// ---------------------------------------------------------------------------
// Kernel 1: PURE GEMV partial stream — R8's measured-32.6us kernel, verbatim.
// (block 0 additionally zeroes g_oacc: one predicated store, invisible.)
// ---------------------------------------------------------------------------
__global__ void __launch_bounds__(256)
k_recur(const float* __restrict__ hidden, const float* __restrict__ hebb,
        const float* __restrict__ w,      const float* __restrict__ plas) {
    int b = blockIdx.x, t = threadIdx.x;
    if (b == 0 && t < OUT) g_oacc[t] = 0.f;

    int stripe = b >> 1;
    int j8 = (b & 1) * 256 + t;            // 0..511
    int k0 = (stripe * H) / GY;
    int k1 = ((stripe + 1) * H) / GY;

    const float4* w4 = (const float4*)w;
    const float4* p4 = (const float4*)plas;
    const float4* h4 = (const float4*)hebb;

    float4 acc0 = make_float4(0.f, 0.f, 0.f, 0.f);
    float4 acc1 = make_float4(0.f, 0.f, 0.f, 0.f);
    size_t fbase = (size_t)j8 * 2;
#pragma unroll 4
    for (int r = k0; r < k1; ++r) {
        size_t idx = (size_t)r * NJ4 + fbase;
        float hk = __ldg(hidden + r);
        float4 a0 = w4[idx], a1 = w4[idx + 1];
        float4 b0 = p4[idx], b1 = p4[idx + 1];
        float4 c0, c1;
        asm volatile(
            "ld.global.nc.L2::evict_last.v8.b32 "
            "{%0,%1,%2,%3,%4,%5,%6,%7}, [%8];"
            : "=f"(c0.x), "=f"(c0.y), "=f"(c0.z), "=f"(c0.w),
              "=f"(c1.x), "=f"(c1.y), "=f"(c1.z), "=f"(c1.w)
            : "l"(h4 + idx));
        acc0.x += hk * fmaf(b0.x, c0.x, a0.x);
        acc0.y += hk * fmaf(b0.y, c0.y, a0.y);
        acc0.z += hk * fmaf(b0.z, c0.z, a0.z);
        acc0.w += hk * fmaf(b0.w, c0.w, a0.w);
        acc1.x += hk * fmaf(b1.x, c1.x, a1.x);
        acc1.y += hk * fmaf(b1.y, c1.y, a1.y);
        acc1.z += hk * fmaf(b1.z, c1.z, a1.z);
        acc1.w += hk * fmaf(b1.w, c1.w, a1.w);
    }
    size_t o = (size_t)stripe * NJ4 + fbase;
    g_part[o]     = acc0;
    g_part[o + 1] = acc1;
}

// ---------------------------------------------------------------------------
// Kernel 2: ALL the glue (129 blocks; machine otherwise idle, inherent
// serial point between the two streams).
//  blocks 0..127: i2h dots (own 32 cols, smem) + reduce partials + relu x
//                 + partial out-head dots -> atomicAdd g_oacc -> bump done.
//  block 128:     ticket-wait reducers -> out = tanh(g_oacc + b_h2o).
// ---------------------------------------------------------------------------
__global__ void __launch_bounds__(256)
k_glue(const float* __restrict__ inp,   const float* __restrict__ W_i2h,
       const float* __restrict__ b_i2h, const float* __restrict__ W_h2o,
       const float* __restrict__ b_h2o, float* __restrict__ x_out,
       float* __restrict__ out) {
    int b = blockIdx.x, t = threadIdx.x;

    if (b < NRB) {
        __shared__ float4 sp[32][8];
        __shared__ float4 stot[8];
        __shared__ float  sdot[32];      // i2h + bias for own 32 columns
        __shared__ float  xs[32];
        __shared__ float  sacc[4][OUT];
        int j4base = b * 8;              // 8 f4 cols
        int j0     = b * 32;             // first scalar column

        // ---- i2h dots: warp wrp covers rows j0 + wrp*4 .. +3 ----
        int wrp = t >> 5, lane = t & 31;
        const float4* in4 = (const float4*)inp;
#pragma unroll
        for (int c = 0; c < 4; ++c) {
            int row = j0 + wrp * 4 + c;
            const float4* wr = (const float4*)(W_i2h + (size_t)row * IN);
            float d = 0.f;
#pragma unroll
            for (int q = 0; q < (IN / 4) / 32; ++q) {
                float4 aa = wr[lane + q * 32];
                float4 bb = in4[lane + q * 32];
                d += aa.x * bb.x + aa.y * bb.y + aa.z * bb.z + aa.w * bb.w;
            }
#pragma unroll
            for (int o = 16; o; o >>= 1) d += __shfl_down_sync(0xffffffffu, d, o);
            if (lane == 0) sdot[wrp * 4 + c] = d + b_i2h[row];
        }

        // ---- reduce partials (coalesced 128B rows; g_part ready: k1 done) --
        int j4loc = t & 7;
        int grp   = t >> 3;              // 0..31
        float4 acc = make_float4(0.f, 0.f, 0.f, 0.f);
#pragma unroll
        for (int q = 0; q < (GY + 31) / 32; ++q) {
            int kb = grp + 32 * q;
            if (kb < GY) {
                float4 v = g_part[(size_t)kb * NJ4 + j4base + j4loc];
                acc.x += v.x; acc.y += v.y; acc.z += v.z; acc.w += v.w;
            }
        }
        sp[grp][j4loc] = acc;
        __syncthreads();
        if (t < 8) {
            float4 t4 = make_float4(0.f, 0.f, 0.f, 0.f);
#pragma unroll
            for (int g = 0; g < 32; ++g) {
                float4 v = sp[g][t];
                t4.x += v.x; t4.y += v.y; t4.z += v.z; t4.w += v.w;
            }
            stot[t] = t4;
        }
        __syncthreads();
        if (t < 32) {
            int jl = t >> 2, comp = t & 3;
            float4 t4 = stot[jl];
            float part = (comp == 0) ? t4.x : (comp == 1) ? t4.y
                       : (comp == 2) ? t4.z : t4.w;
            int j = j0 + t;
            float v = fmaxf(part + sdot[t], 0.f);
            g_x[j]   = v;
            x_out[j] = v;
            xs[t]    = v;
        }
        __syncthreads();

        // ---- partial out-head: own 32 columns vs all 64 outputs ----
        {
            int o = t & 63;
            int g = t >> 6;              // 0..3, 8 cols each
            float p = 0.f;
#pragma unroll
            for (int c = 0; c < 8; ++c)
                p += W_h2o[(size_t)o * H + j0 + g * 8 + c] * xs[g * 8 + c];
            sacc[g][o] = p;
        }
        __syncthreads();
        if (t < OUT)
            atomicAdd(&g_oacc[t], sacc[0][t] + sacc[1][t] + sacc[2][t] + sacc[3][t]);
        __threadfence();
        __syncthreads();
        if (t == 0) atomicAdd(&g_done2, 1u);
        return;
    }

    // ---- out-finalize (block 128) ----
    if (t == 0) {
        unsigned tk = atomicAdd(&g_otkt, 1u);
        unsigned target = (tk + 1u) * NRB;
        volatile unsigned* p = &g_done2;
        while (*p < target) __nanosleep(64);
    }
    __syncthreads();
    __threadfence();
    if (t < OUT) out[t] = tanhf(g_oacc[t] + b_h2o[t]);
}

// ---------------------------------------------------------------------------
// Kernel 3: PURE hebb update — R14's measured-20.35us kernel, verbatim.
// ---------------------------------------------------------------------------
__global__ void __launch_bounds__(256)
k_hebb(const float* __restrict__ hidden,
       const float* __restrict__ hebb,
       const float* __restrict__ learn_p,
       float* __restrict__ hebb_out) {
    int idx = blockIdx.x * blockDim.x + threadIdx.x;  // float4 index
    int k   = idx >> 10;
    int jc  = idx & 1023;
    float learn = __ldg(learn_p);
    float hk    = __ldg(hidden + k);
    float4 hb = ((const float4*)hebb)[idx];
    float4 xv = ((const float4*)g_x)[jc];
    float a = 1.f - learn;
    float s = learn * hk;
    float4 o;
    o.x = fmaf(a, hb.x, s * xv.x);
    o.y = fmaf(a, hb.y, s * xv.y);
    o.z = fmaf(a, hb.z, s * xv.z);
    o.w = fmaf(a, hb.w, s * xv.w);
    ((float4*)hebb_out)[idx] = o;
}

// ---------------------------------------------------------------------------
// Inputs: 0 inp, 1 hidden, 2 hebb, 3 W_i2h, 4 b_i2h, 5 w, 6 plas,
//         7 learn, 8 W_h2o, 9 b_h2o
// Output: [out(64) | x(4096) | hebb_new(16777216)]
// ---------------------------------------------------------------------------
extern "C" void kernel_launch(void* const* d_in, const int* in_sizes, int n_in,
                              void* d_out, int out_size) {
    const float* inp    = (const float*)d_in[0];
    const float* hidden = (const float*)d_in[1];
    const float* hebb   = (const float*)d_in[2];
    const float* W_i2h  = (const float*)d_in[3];
    const float* b_i2h  = (const float*)d_in[4];
    const float* w      = (const float*)d_in[5];
    const float* plas   = (const float*)d_in[6];
    const float* learn  = (const float*)d_in[7];
    const float* W_h2o  = (const float*)d_in[8];
    const float* b_h2o  = (const float*)d_in[9];

    float* out      = (float*)d_out;
    float* x_out    = out + OUT;
    float* hebb_out = out + OUT + H;

    // 1) pure GEMV partial stream
    k_recur<<<NSB, 256>>>(hidden, hebb, w, plas);

    // 2) all glue: i2h + reduce + relu x + output head
    k_glue<<<NRB + 1, 256>>>(inp, W_i2h, b_i2h, W_h2o, b_h2o, x_out, out);

    // 3) pure hebb update
    k_hebb<<<(H * H / 4) / 256, 256>>>(hidden, hebb, learn, hebb_out);
}